// round 10
// baseline (speedup 1.0000x reference)
#include <cuda_runtime.h>
#include <cuda_bf16.h>
#include <cuda_fp16.h>

#define NCLUST 256
#define NPT    128
#define NEDGE  1024
#define VS     32
#define VOXN   (VS*VS*VS)   // 32768

typedef unsigned long long ull;

__device__ __forceinline__ ull pk2(float lo, float hi) {
    ull r; asm("mov.b64 %0, {%1,%2};" : "=l"(r) : "f"(lo), "f"(hi)); return r;
}
__device__ __forceinline__ void fma2(ull& d, ull a, ull b) {
    asm("fma.rn.f32x2 %0, %1, %2, %0;" : "+l"(d) : "l"(a), "l"(b));
}
__device__ __forceinline__ float2 upk2(ull v) {
    float2 r; asm("mov.b64 {%0,%1}, %2;" : "=f"(r.x), "=f"(r.y) : "l"(v)); return r;
}
__device__ __forceinline__ unsigned smem_u32(const void* p) {
    unsigned a;
    asm("{ .reg .u64 t; cvta.to.shared.u64 t, %1; cvt.u32.u64 %0, t; }" : "=r"(a) : "l"(p));
    return a;
}

// Scratch (device globals)
__device__ float  g_cvox[NCLUST * VOXN];             // 32 MB
__device__ float  g_c1c[NCLUST * 4096 * 16];         // 67 MB, layout [c][sp][ic]
__device__ float  g_c2[NEDGE * 32 * 512];            // 67 MB, layout [e][oc][sp]
__device__ float  g_w3t[32 * 27 * 64];               // W3 -> [ic][tap][oc]
__device__ __align__(16) __half g_w2h[32 * 448];     // W2 fp16 [oc][tap*16+ic], K pad 448
__device__ int    g_eidx_is_i64;
__device__ int    g_mask_is_u8;

// ---------------------------------------------------------------------------
// Kernel D: dtype layout detection
// ---------------------------------------------------------------------------
__global__ void detect_kernel(const int* __restrict__ eidx_w,
                              const unsigned int* __restrict__ mask_w,
                              int E, int maskWords)
{
    __shared__ int oddNZ, bigW;
    if (threadIdx.x == 0) { oddNZ = 0; bigW = 0; }
    __syncthreads();
    for (int i = threadIdx.x; i < E; i += blockDim.x)
        if (eidx_w[2 * i + 1] != 0) atomicOr(&oddNZ, 1);
    for (int i = threadIdx.x; i < maskWords; i += blockDim.x)
        if (mask_w[i] > 1u) atomicOr(&bigW, 1);
    __syncthreads();
    if (threadIdx.x == 0) {
        g_eidx_is_i64 = (oddNZ == 0) ? 1 : 0;
        g_mask_is_u8  = bigW;
    }
}

// ---------------------------------------------------------------------------
// Kernel W: W3 -> [ic][tap][oc] fp32; W2 -> fp16 [oc][448]
// ---------------------------------------------------------------------------
__global__ void wtrans_kernel(const float* __restrict__ W2,
                              const float* __restrict__ W3)
{
    int i = blockIdx.x * blockDim.x + threadIdx.x;
    if (i < 64 * 32 * 27) {
        int oc = i / (32 * 27), r = i % (32 * 27), ic = r / 27, tap = r % 27;
        g_w3t[(ic * 27 + tap) * 64 + oc] = W3[i];
    }
    if (i < 32 * 448) {
        int oc = i / 448, k = i % 448;
        float v = 0.0f;
        if (k < 432) {
            int tap = k >> 4, ic = k & 15;
            v = W2[(oc * 16 + ic) * 27 + tap];
        }
        g_w2h[i] = __float2half(v);
    }
}

// ---------------------------------------------------------------------------
// Kernel 0: per-cluster voxelization (ovx/ovy/ovz tables, dynamic smem)
// ---------------------------------------------------------------------------
#define VOX_SMEM ((3 * NPT * VS + 4 * NPT + 6 * NPT) * 4)   // 54272 B

__global__ __launch_bounds__(256) void vox_kernel(
    const float* __restrict__ data,
    const int* __restrict__ clusts,
    const void* __restrict__ cmask)
{
    extern __shared__ __align__(16) float dsmv[];
    float* ovy = dsmv;
    float* ovz = dsmv + NPT * VS;
    float* ovx = dsmv + 2 * NPT * VS;
    float* sw  = dsmv + 3 * NPT * VS;
    float* spx = sw  + NPT;
    float* spy = spx + NPT;
    float* spz = spy + NPT;
    float* red = spz + NPT;

    const int c = blockIdx.x;
    const int t = threadIdx.x;
    const int mask_u8 = g_mask_is_u8;

    if (t < NPT) {
        int idx = clusts[c * NPT + t];
        int m;
        if (mask_u8) m = ((const unsigned char*)cmask)[c * NPT + t];
        else         m = ((const int*)cmask)[c * NPT + t];
        float x = data[idx * 5 + 0];
        float y = data[idx * 5 + 1];
        float z = data[idx * 5 + 2];
        float v = data[idx * 5 + 4];
        spx[t] = x; spy[t] = y; spz[t] = z;
        sw[t]  = m ? v : 0.0f;
        red[0*NPT + t] = m ? x :  1e9f;
        red[1*NPT + t] = m ? y :  1e9f;
        red[2*NPT + t] = m ? z :  1e9f;
        red[3*NPT + t] = m ? x : -1e9f;
        red[4*NPT + t] = m ? y : -1e9f;
        red[5*NPT + t] = m ? z : -1e9f;
    }
    __syncthreads();
    for (int s = 64; s > 0; s >>= 1) {
        if (t < s) {
            red[0*NPT + t] = fminf(red[0*NPT + t], red[0*NPT + t + s]);
            red[1*NPT + t] = fminf(red[1*NPT + t], red[1*NPT + t + s]);
            red[2*NPT + t] = fminf(red[2*NPT + t], red[2*NPT + t + s]);
            red[3*NPT + t] = fmaxf(red[3*NPT + t], red[3*NPT + t + s]);
            red[4*NPT + t] = fmaxf(red[4*NPT + t], red[4*NPT + t + s]);
            red[5*NPT + t] = fmaxf(red[5*NPT + t], red[5*NPT + t + s]);
        }
        __syncthreads();
    }
    const float minx = red[0], miny = red[NPT], minz = red[2*NPT];
    const float rx = red[3*NPT] - minx;
    const float ry = red[4*NPT] - miny;
    const float rz = red[5*NPT] - minz;
    const float mr = fmaxf(rx, fmaxf(ry, rz)) + 1.0f;
    const float gs  = 1.0f / mr;
    const float rgs = mr;
    const float ns  = 1.0f / (float)VS;

    {
        int p    = t & (NPT - 1);
        int half = t >> 7;
        float vx = (spx[p] - minx - rx * 0.5f - 0.5f) * gs + 0.5f;
        float vy = (spy[p] - miny - ry * 0.5f - 0.5f) * gs + 0.5f;
        float vz = (spz[p] - minz - rz * 0.5f - 0.5f) * gs + 0.5f;
        for (int b = half * 16; b < half * 16 + 16; ++b) {
            float lo = (float)b * ns;
            float ox = fminf(vx + gs, lo + ns) - fmaxf(vx, lo);
            float oy = fminf(vy + gs, lo + ns) - fmaxf(vy, lo);
            float oz = fminf(vz + gs, lo + ns) - fmaxf(vz, lo);
            ovx[p * VS + b] = fmaxf(ox, 0.0f) * rgs;
            ovy[p * VS + b] = fmaxf(oy, 0.0f) * rgs;
            ovz[p * VS + b] = fmaxf(oz, 0.0f) * rgs;
        }
    }
    __syncthreads();

    float* outp = g_cvox + (size_t)c * VOXN;
    for (int pass = 0; pass < 4; ++pass) {
        int jk = t + pass * 256;
        int j = jk >> 5, k = jk & 31;
        float acc[VS];
#pragma unroll
        for (int i = 0; i < VS; ++i) acc[i] = 0.0f;
        for (int p = 0; p < NPT; ++p) {
            float ty = sw[p] * ovy[p * VS + j];
            if (ty != 0.0f) {
                float tz = ty * ovz[p * VS + k];
                const float4* ox4 = (const float4*)&ovx[p * VS];
#pragma unroll
                for (int i4 = 0; i4 < 8; ++i4) {
                    float4 o = ox4[i4];
                    acc[i4 * 4 + 0] += o.x * tz;
                    acc[i4 * 4 + 1] += o.y * tz;
                    acc[i4 * 4 + 2] += o.z * tz;
                    acc[i4 * 4 + 3] += o.w * tz;
                }
            }
        }
#pragma unroll
        for (int i = 0; i < VS; ++i)
            outp[i * (VS * VS) + jk] = acc[i];
    }
}

// ---------------------------------------------------------------------------
// Kernel 1: per-CLUSTER linear conv1, z-slab tiling. Output [sp][ic].
// ---------------------------------------------------------------------------
#define C1SD 36
#define C1PL (33 * C1SD)     // 1188
#define C1SZ (9 * C1PL)      // 10692 floats

__global__ __launch_bounds__(256, 2) void conv1c_kernel(
    const float* __restrict__ W1)
{
    __shared__ __align__(16) float s_in[C1SZ];
    __shared__ __align__(16) float s_w[27 * 16];

    const int c    = blockIdx.x >> 2;
    const int slab = blockIdx.x & 3;
    const int t = threadIdx.x;
    const float* __restrict__ A = g_cvox + (size_t)c * VOXN;

    for (int i = t; i < C1SZ; i += 256) s_in[i] = 0.0f;
    for (int i = t; i < 432; i += 256) {
        int oc = i / 27, tap = i % 27;
        s_w[tap * 16 + oc] = W1[i];
    }
    __syncthreads();

    const int z0 = slab * 8;
#pragma unroll
    for (int r = 0; r < 9; ++r) {
        int i4 = t + r * 256;
        int zz = i4 >> 8, j = i4 & 255;
        int gz = z0 + zz;
        if (gz < 32) {
            float4 v = *(const float4*)&A[gz * 1024 + j * 4];
            *(float4*)&s_in[zz * C1PL + (j >> 3) * C1SD + (j & 7) * 4] = v;
        }
    }
    __syncthreads();

    const int x = t & 15, y = t >> 4;

    ull acc[4][8];
#pragma unroll
    for (int q = 0; q < 4; ++q)
#pragma unroll
        for (int m = 0; m < 8; ++m) acc[q][m] = 0ULL;

#pragma unroll
    for (int dz = 0; dz < 3; ++dz)
#pragma unroll
        for (int dy = 0; dy < 3; ++dy) {
            float2 v01[4];
            float  v2s[4];
#pragma unroll
            for (int q = 0; q < 4; ++q) {
                const int o = (2 * q + dz) * C1PL + (2 * y + dy) * C1SD + 2 * x;
                v01[q] = *(const float2*)&s_in[o];
                v2s[q] = s_in[o + 2];
            }
#pragma unroll
            for (int dx = 0; dx < 3; ++dx) {
                const int tap = (dz * 3 + dy) * 3 + dx;
                const ulonglong2 w01 = *(const ulonglong2*)&s_w[tap * 16];
                const ulonglong2 w23 = *(const ulonglong2*)&s_w[tap * 16 + 4];
                const ulonglong2 w45 = *(const ulonglong2*)&s_w[tap * 16 + 8];
                const ulonglong2 w67 = *(const ulonglong2*)&s_w[tap * 16 + 12];
#pragma unroll
                for (int q = 0; q < 4; ++q) {
                    float v = (dx == 0) ? v01[q].x : (dx == 1) ? v01[q].y : v2s[q];
                    ull vv = pk2(v, v);
                    fma2(acc[q][0], vv, w01.x);
                    fma2(acc[q][1], vv, w01.y);
                    fma2(acc[q][2], vv, w23.x);
                    fma2(acc[q][3], vv, w23.y);
                    fma2(acc[q][4], vv, w45.x);
                    fma2(acc[q][5], vv, w45.y);
                    fma2(acc[q][6], vv, w67.x);
                    fma2(acc[q][7], vv, w67.y);
                }
            }
        }

    float* outp = g_c1c + (size_t)c * 4096 * 16;
#pragma unroll
    for (int q = 0; q < 4; ++q) {
        const int oz = slab * 4 + q;
        const int sp = oz * 256 + y * 16 + x;
        float vals[16];
#pragma unroll
        for (int m = 0; m < 8; ++m) {
            float2 p = upk2(acc[q][m]);
            vals[2 * m] = p.x; vals[2 * m + 1] = p.y;
        }
        float4* o4 = (float4*)(outp + sp * 16);
#pragma unroll
        for (int w = 0; w < 4; ++w) o4[w] = ((float4*)vals)[w];
    }
}

// ---------------------------------------------------------------------------
// Kernel 2: conv2 via mma.sync m16n8k16 (fp16 in, fp32 acc) — baseline PTX,
// no sm_103a-only features. Per edge: D[512,32] = im2col[512,432] x W2^T.
// Act smem: parity-split x, 48B voxel stride (conflict-free ldmatrix).
// ---------------------------------------------------------------------------
#define C2_B_ROWB   912                        // 456 fp16 per oc row
#define C2_B_BYTES  (32 * C2_B_ROWB)           // 29184
#define C2_ACT_BYTES (5 * 17 * 18 * 48)        // 73440
#define C2_STAGE_F  (4 * 16 * 34)              // 2176 floats
#define C2MM_SMEM   (C2_B_BYTES + C2_ACT_BYTES + C2_STAGE_F * 4 + 64)

__global__ __launch_bounds__(128) void conv2_mma_kernel(
    const int* __restrict__ eidx,
    const float* __restrict__ b2,
    const float* __restrict__ b1,
    int E, int C)
{
    extern __shared__ __align__(16) char sm2[];
    char*  sB     = sm2;
    char*  sAct   = sm2 + C2_B_BYTES;
    float* sStage = (float*)(sm2 + C2_B_BYTES + C2_ACT_BYTES);
    float* sB1    = sStage + C2_STAGE_F;

    const int e = blockIdx.x;
    const int t = threadIdx.x;
    const int w = t >> 5, lane = t & 31;

    int ca, cb;
    if (g_eidx_is_i64) { ca = eidx[2 * e]; cb = eidx[2 * (E + e)]; }
    else               { ca = eidx[e];     cb = eidx[E + e];       }
    ca = min(max(ca, 0), C - 1);
    cb = min(max(cb, 0), C - 1);

    if (t < 16) sB1[t] = b1[t];

    // B fill: g_w2h [32][448] fp16 -> sB [32][456] rows (912B stride)
    {
        const unsigned* w2u = (const unsigned*)g_w2h;   // 32 x 224 u32
        for (int j = t; j < 32 * 224; j += 128) {
            int row = j / 224, ku = j % 224;
            *(unsigned*)(sB + row * C2_B_ROWB + ku * 4) = w2u[j];
        }
    }
    __syncthreads();

    const float4* __restrict__ A4 = (const float4*)(g_c1c + (size_t)ca * 65536);
    const float4* __restrict__ B4 = (const float4*)(g_c1c + (size_t)cb * 65536);
    const float4* b1q = (const float4*)sB1;

    // per-thread mma constants
    const int xr   = lane & 7;
    const int ysel = (lane >> 3) & 1;
    const int hh   = (lane >> 4) & 1;
    const int zloc = w & 1, ypg = w >> 1;
    const unsigned actB = smem_u32(sAct);
    const unsigned bBs  = smem_u32(sB);
    // B-ldmatrix per-thread address pieces
    const int bgrp = lane >> 3, brow = lane & 7;
    const unsigned bAddr0 = bBs + (unsigned)(((bgrp >> 1) * 8 + brow) * C2_B_ROWB
                                             + (bgrp & 1) * 16);
    float* stage = sStage + w * (16 * 34);
    float* outp = g_c2 + (size_t)e * 32 * 512;
    const float bias2 = __ldg(&b2[lane]);

    for (int t2 = 0; t2 < 4; ++t2) {
        // ---- act fill: 5 planes, channel-last fp16, relu(linA+linB+b1)
        for (int r = 0; r < 46; ++r) {
            int i = t + r * 128;
            if (i < 5780) {
                int icq = i & 3, v = i >> 2;
                int p = v / 289, rem = v % 289, yy = rem / 17, xx = rem % 17;
                int zz = t2 * 4 + p;
                uint2 st = make_uint2(0u, 0u);
                if (zz < 16 && yy < 16 && xx < 16) {
                    int gi = ((zz * 16 + yy) * 16 + xx) * 4 + icq;
                    float4 a = A4[gi], b = B4[gi], bb = b1q[icq];
                    __half2 h0 = __floats2half2_rn(fmaxf(a.x + b.x + bb.x, 0.0f),
                                                   fmaxf(a.y + b.y + bb.y, 0.0f));
                    __half2 h1 = __floats2half2_rn(fmaxf(a.z + b.z + bb.z, 0.0f),
                                                   fmaxf(a.w + b.w + bb.w, 0.0f));
                    st.x = *(unsigned*)&h0;
                    st.y = *(unsigned*)&h1;
                }
                int voff = ((p * 17 + yy) * 18 + (xx & 1) * 9 + (xx >> 1)) * 48 + icq * 8;
                *(uint2*)(sAct + voff) = st;
            }
        }
        __syncthreads();

        float acc[2][16];
#pragma unroll
        for (int m = 0; m < 2; ++m)
#pragma unroll
            for (int q = 0; q < 16; ++q) acc[m][q] = 0.0f;

#pragma unroll
        for (int dz = 0; dz < 3; ++dz)
#pragma unroll
            for (int dy = 0; dy < 3; ++dy)
#pragma unroll
                for (int dx = 0; dx < 3; ++dx) {
                    const int g = (dz * 3 + dy) * 3 + dx;
                    // B fragments: 2x ldmatrix.x4 -> 4 n-tiles
                    unsigned bf[8];
                    {
                        unsigned a0 = bAddr0 + (unsigned)(g * 32);
                        asm volatile(
                            "ldmatrix.sync.aligned.m8n8.x4.shared.b16 {%0,%1,%2,%3}, [%4];"
                            : "=r"(bf[0]), "=r"(bf[1]), "=r"(bf[2]), "=r"(bf[3])
                            : "r"(a0));
                        asm volatile(
                            "ldmatrix.sync.aligned.m8n8.x4.shared.b16 {%0,%1,%2,%3}, [%4];"
                            : "=r"(bf[4]), "=r"(bf[5]), "=r"(bf[6]), "=r"(bf[7])
                            : "r"(a0 + 16u * C2_B_ROWB));
                    }
                    const int p = 2 * zloc + dz;
                    const int parity = dx & 1;
                    const int xh = xr + (dx >> 1);
#pragma unroll
                    for (int mtl = 0; mtl < 2; ++mtl) {
                        const int ypair = ypg * 2 + mtl;
                        const int yv = 4 * ypair + 2 * ysel + dy;
                        unsigned aAddr = actB
                            + (unsigned)(((p * 17 + yv) * 18 + parity * 9 + xh) * 48
                                         + hh * 16);
                        unsigned af[4];
                        asm volatile(
                            "ldmatrix.sync.aligned.m8n8.x4.shared.b16 {%0,%1,%2,%3}, [%4];"
                            : "=r"(af[0]), "=r"(af[1]), "=r"(af[2]), "=r"(af[3])
                            : "r"(aAddr));
#pragma unroll
                        for (int nt = 0; nt < 4; ++nt) {
                            float* c = &acc[mtl][nt * 4];
                            asm volatile(
                                "mma.sync.aligned.m16n8k16.row.col.f32.f16.f16.f32 "
                                "{%0,%1,%2,%3}, {%4,%5,%6,%7}, {%8,%9}, {%0,%1,%2,%3};"
                                : "+f"(c[0]), "+f"(c[1]), "+f"(c[2]), "+f"(c[3])
                                : "r"(af[0]), "r"(af[1]), "r"(af[2]), "r"(af[3]),
                                  "r"(bf[nt * 2]), "r"(bf[nt * 2 + 1]));
                        }
                    }
                }

        // ---- epilogue: stage -> coalesced STG with bias+relu
#pragma unroll
        for (int mtl = 0; mtl < 2; ++mtl) {
            const int row = lane >> 2, col2 = (lane & 3) * 2;
#pragma unroll
            for (int nt = 0; nt < 4; ++nt) {
                const int cb0 = nt * 8 + col2;
                *(float2*)&stage[row * 34 + cb0]       =
                    make_float2(acc[mtl][nt * 4 + 0], acc[mtl][nt * 4 + 1]);
                *(float2*)&stage[(row + 8) * 34 + cb0] =
                    make_float2(acc[mtl][nt * 4 + 2], acc[mtl][nt * 4 + 3]);
            }
            __syncwarp();
            {
                const int z = t2 * 2 + zloc;
                const int ypair = ypg * 2 + mtl;
                const int spb = z * 64 + ypair * 16;
                float o[16];
#pragma unroll
                for (int sp = 0; sp < 16; ++sp)
                    o[sp] = fmaxf(stage[sp * 34 + lane] + bias2, 0.0f);
                float4* dst = (float4*)&outp[lane * 512 + spb];
#pragma unroll
                for (int q = 0; q < 4; ++q) dst[q] = ((float4*)o)[q];
            }
            __syncwarp();
        }
        __syncthreads();
    }
}

// ---------------------------------------------------------------------------
// Kernel 3: conv3 (32->64ch) + relu + mean-pool + FC (fp32 FFMA2)
// ---------------------------------------------------------------------------
#define C3S1 12
#define C3S2 108
#define C3SZ (9*C3S2)      // 972

__global__ __launch_bounds__(256, 3) void conv3_kernel(
    const float* __restrict__ b3,
    const float* __restrict__ Wfc,
    const float* __restrict__ bfc,
    float* __restrict__ out)
{
    __shared__ __align__(16) float s_in[2][C3SZ];
    __shared__ __align__(16) float s_w[2][27 * 64];
    __shared__ __align__(16) float s_pool[64 * 65];
    __shared__ __align__(16) float s_pooled[64];

    const int e = blockIdx.x;
    const int t = threadIdx.x;
    const int og = t >> 6;
    const int s  = t & 63;
    const int lx = s & 3, ly = (s >> 2) & 3, lz = s >> 4;

    for (int i = t; i < 2 * C3SZ; i += 256) ((float*)s_in)[i] = 0.0f;

    ull acc[8];
#pragma unroll
    for (int m = 0; m < 8; ++m) acc[m] = 0ULL;

    const float4* __restrict__ src4 = (const float4*)(g_c2 + (size_t)e * 32 * 512);

    for (int ics = 0; ics < 32; ics += 2) {
        __syncthreads();
        {
            int buf = t >> 7, j = t & 127;
            float4 v = src4[(ics + buf) * 128 + j];
            int i = j * 4;
            int x = i & 7, y = (i >> 3) & 7, z = i >> 6;
            *(float4*)&s_in[buf][z * C3S2 + y * C3S1 + x] = v;
        }
        {
            const float4* wsrc = (const float4*)(g_w3t + ics * 1728);
            float4* wdst = (float4*)s_w;
#pragma unroll
            for (int r = 0; r < 4; ++r) {
                int i4 = t + r * 256;
                if (i4 < 864) wdst[i4] = wsrc[i4];
            }
        }
        __syncthreads();
#pragma unroll
        for (int buf = 0; buf < 2; ++buf) {
            const float* sin = s_in[buf];
            const float* sw  = s_w[buf];
#pragma unroll
            for (int dz = 0; dz < 3; ++dz)
#pragma unroll
                for (int dy = 0; dy < 3; ++dy) {
                    const int o = (2 * lz + dz) * C3S2 + (2 * ly + dy) * C3S1 + 2 * lx;
                    const float2 v01 = *(const float2*)&sin[o];
                    const float  v2s = sin[o + 2];
#pragma unroll
                    for (int dx = 0; dx < 3; ++dx) {
                        const int tap = (dz * 3 + dy) * 3 + dx;
                        const ulonglong2 w0 = *(const ulonglong2*)&sw[tap * 64 + og * 16];
                        const ulonglong2 w1 = *(const ulonglong2*)&sw[tap * 64 + og * 16 + 4];
                        const ulonglong2 w2 = *(const ulonglong2*)&sw[tap * 64 + og * 16 + 8];
                        const ulonglong2 w3 = *(const ulonglong2*)&sw[tap * 64 + og * 16 + 12];
                        float v = (dx == 0) ? v01.x : (dx == 1) ? v01.y : v2s;
                        ull vv = pk2(v, v);
                        fma2(acc[0], vv, w0.x);
                        fma2(acc[1], vv, w0.y);
                        fma2(acc[2], vv, w1.x);
                        fma2(acc[3], vv, w1.y);
                        fma2(acc[4], vv, w2.x);
                        fma2(acc[5], vv, w2.y);
                        fma2(acc[6], vv, w3.x);
                        fma2(acc[7], vv, w3.y);
                    }
                }
        }
    }
    __syncthreads();
#pragma unroll
    for (int m = 0; m < 8; ++m) {
        float2 p = upk2(acc[m]);
        const int oc0 = og * 16 + 2 * m;
        s_pool[s * 65 + oc0]     = fmaxf(p.x + __ldg(&b3[oc0]),     0.0f);
        s_pool[s * 65 + oc0 + 1] = fmaxf(p.y + __ldg(&b3[oc0 + 1]), 0.0f);
    }
    __syncthreads();
    if (t < 64) {
        float sum = 0.0f;
#pragma unroll 8
        for (int sp = 0; sp < 64; ++sp) sum += s_pool[sp * 65 + t];
        s_pooled[t] = sum * (1.0f / 64.0f);
    }
    __syncthreads();
    if (t < 64) {
        float r = bfc[t];
#pragma unroll 8
        for (int ic = 0; ic < 64; ++ic)
            r += s_pooled[ic] * __ldg(&Wfc[ic * 64 + t]);
        out[e * 64 + t] = r;
    }
}

// ---------------------------------------------------------------------------
extern "C" void kernel_launch(void* const* d_in, const int* in_sizes, int n_in,
                              void* d_out, int out_size)
{
    const float* data   = (const float*)d_in[0];
    const int*   clusts = (const int*)d_in[1];
    const void*  cmask  = d_in[2];
    const int*   eidx   = (const int*)d_in[3];
    const float* W1     = (const float*)d_in[4];
    const float* b1     = (const float*)d_in[5];
    const float* W2     = (const float*)d_in[6];
    const float* b2     = (const float*)d_in[7];
    const float* W3     = (const float*)d_in[8];
    const float* b3     = (const float*)d_in[9];
    const float* Wfc    = (const float*)d_in[10];
    const float* bfc    = (const float*)d_in[11];
    float*       out    = (float*)d_out;

    const int C = in_sizes[1] / NPT;   // 256
    const int E = in_sizes[3] / 2;     // 1024
    const int maskWords = in_sizes[2] / 4;

    cudaFuncSetAttribute(vox_kernel,
        cudaFuncAttributeMaxDynamicSharedMemorySize, VOX_SMEM);
    cudaFuncSetAttribute(conv2_mma_kernel,
        cudaFuncAttributeMaxDynamicSharedMemorySize, C2MM_SMEM);

    detect_kernel<<<1, 256>>>(eidx, (const unsigned int*)cmask, E, maskWords);
    wtrans_kernel<<<216, 256>>>(W2, W3);
    vox_kernel<<<C, 256, VOX_SMEM>>>(data, clusts, cmask);
    conv1c_kernel<<<C * 4, 256>>>(W1);
    conv2_mma_kernel<<<E, 128, C2MM_SMEM>>>(eidx, b2, b1, E, C);
    conv3_kernel<<<E, 256>>>(b3, Wfc, bfc, out);
}